// round 8
// baseline (speedup 1.0000x reference)
#include <cuda_runtime.h>

#define NN    30000
#define NE    600000
#define C_IN  256
#define C_HID 128
#define C_OUT 64

// ---------------- scratch (device globals — no allocation allowed) ----------
__device__ int   g_deg[NN];
__device__ float g_dinv[NN];
__device__ int   g_rowptr[NN + 1];
__device__ int   g_cursor[NN];
__device__ int   g_col[NE];
__device__ int   g_is64;
__device__ float g_hs1[(size_t)NN * C_HID];   // dinv * (X @ W1)
__device__ float g_h2 [(size_t)NN * C_HID];   // relu(agg1 + b1)
__device__ float g_hs2[(size_t)NN * C_OUT];   // dinv * (h2 @ W2)

// ---------------- edge dtype detection (int64 vs int32) ---------------------
__global__ void detect_kernel(const long long* __restrict__ p) {
    if (blockIdx.x == 0 && threadIdx.x == 0) {
        int ok = 1;
        for (int e = 0; e < 64; e++) {
            long long v = p[e];
            if (v < 0 || v >= NN) { ok = 0; break; }
        }
        g_is64 = ok;
    }
}

// ---------------- CSR build --------------------------------------------------
__global__ void zero_deg_kernel() {
    int i = blockIdx.x * blockDim.x + threadIdx.x;
    if (i < NN) g_deg[i] = 0;
}

__global__ void count_deg_kernel(const void* __restrict__ ei) {
    int e = blockIdx.x * blockDim.x + threadIdx.x;
    if (e >= NE) return;
    int d;
    if (g_is64) d = (int)((const long long*)ei)[NE + e];
    else        d = ((const int*)ei)[NE + e];
    atomicAdd(&g_deg[d], 1);
}

__global__ void dinv_kernel() {
    int i = blockIdx.x * blockDim.x + threadIdx.x;
    if (i < NN) g_dinv[i] = rsqrtf((float)(g_deg[i] + 1));  // +1 self loop
}

// single-block chunked exclusive scan over g_deg -> g_rowptr / g_cursor
__global__ void scan_kernel() {
    __shared__ int sh[1024];
    int tid = threadIdx.x;
    int carry = 0;
    for (int base = 0; base < NN; base += 1024) {
        int i = base + tid;
        int v = (i < NN) ? g_deg[i] : 0;
        sh[tid] = v;
        __syncthreads();
        #pragma unroll
        for (int off = 1; off < 1024; off <<= 1) {
            int t = (tid >= off) ? sh[tid - off] : 0;
            __syncthreads();
            sh[tid] += t;
            __syncthreads();
        }
        int excl = carry + sh[tid] - v;
        if (i < NN) { g_rowptr[i] = excl; g_cursor[i] = excl; }
        carry += sh[1023];
        __syncthreads();
    }
    if (tid == 0) g_rowptr[NN] = carry;
}

__global__ void scatter_kernel(const void* __restrict__ ei) {
    int e = blockIdx.x * blockDim.x + threadIdx.x;
    if (e >= NE) return;
    int s, d;
    if (g_is64) {
        s = (int)((const long long*)ei)[e];
        d = (int)((const long long*)ei)[NE + e];
    } else {
        s = ((const int*)ei)[e];
        d = ((const int*)ei)[NE + e];
    }
    int pos = atomicAdd(&g_cursor[d], 1);
    g_col[pos] = s;
}

// ---------------- GEMM with fused dinv row-scale -----------------------------
// C[row, n] = dinv[row] * sum_k X[row,k] * W[k,n]
// BM x BN output tile, BK k-slab, 256 threads, 8x4 micro-tile per thread.
template<int BM, int BN, int BK, int K, int LAYER>
__global__ __launch_bounds__(256)
void gemm_dinv_kernel(const float* __restrict__ Xin, const float* __restrict__ W) {
    static_assert(BM * BN == 256 * 32, "tile/thread mismatch");
    constexpr int TM = 8, TN = 4;
    constexpr int TX = BN / TN;            // threads along n
    constexpr int AQ = BK / 4;             // float4 chunks per A row
    constexpr int LA = BM * AQ / 256;      // A float4 loads per thread
    constexpr int BQ = BN / 4;
    constexpr int LB = BK * BQ / 256;      // B float4 loads per thread

    const float* X;
    float*       out;
    if constexpr (LAYER == 1) { X = Xin;              out = g_hs1; }
    else                      { X = (const float*)g_h2; out = g_hs2; }

    __shared__ float As[BK][BM + 4];       // transposed A slab (row stride 272B/..., 16B aligned)
    __shared__ float Bs[BK][BN];

    const int tid  = threadIdx.x;
    const int tx   = tid % TX;
    const int ty   = tid / TX;
    const int bRow = blockIdx.x * BM;

    float acc[TM][TN];
    #pragma unroll
    for (int m = 0; m < TM; m++)
        #pragma unroll
        for (int n = 0; n < TN; n++) acc[m][n] = 0.f;

    for (int k0 = 0; k0 < K; k0 += BK) {
        #pragma unroll
        for (int l = 0; l < LA; l++) {
            int li = tid + l * 256;
            int r  = li / AQ, cq = li % AQ;
            int grow = bRow + r;
            float4 v = make_float4(0.f, 0.f, 0.f, 0.f);
            if (grow < NN)
                v = *(const float4*)&X[(size_t)grow * K + k0 + cq * 4];
            As[cq * 4 + 0][r] = v.x;
            As[cq * 4 + 1][r] = v.y;
            As[cq * 4 + 2][r] = v.z;
            As[cq * 4 + 3][r] = v.w;
        }
        #pragma unroll
        for (int l = 0; l < LB; l++) {
            int li = tid + l * 256;
            int r  = li / BQ, cq = li % BQ;
            *(float4*)&Bs[r][cq * 4] =
                *(const float4*)&W[(size_t)(k0 + r) * BN + cq * 4];
        }
        __syncthreads();

        #pragma unroll
        for (int kk = 0; kk < BK; kk++) {
            float4 b = *(const float4*)&Bs[kk][tx * TN];
            float4 a0 = *(const float4*)&As[kk][ty * TM];
            float4 a1 = *(const float4*)&As[kk][ty * TM + 4];
            float a[TM] = {a0.x, a0.y, a0.z, a0.w, a1.x, a1.y, a1.z, a1.w};
            #pragma unroll
            for (int m = 0; m < TM; m++) {
                acc[m][0] = fmaf(a[m], b.x, acc[m][0]);
                acc[m][1] = fmaf(a[m], b.y, acc[m][1]);
                acc[m][2] = fmaf(a[m], b.z, acc[m][2]);
                acc[m][3] = fmaf(a[m], b.w, acc[m][3]);
            }
        }
        __syncthreads();
    }

    #pragma unroll
    for (int m = 0; m < TM; m++) {
        int grow = bRow + ty * TM + m;
        if (grow < NN) {
            float s = g_dinv[grow];
            float4 v = make_float4(acc[m][0] * s, acc[m][1] * s,
                                   acc[m][2] * s, acc[m][3] * s);
            *(float4*)&out[(size_t)grow * BN + tx * TN] = v;
        }
    }
}

// ---------------- CSR aggregation: one warp per node -------------------------
// out[i] = (relu?)( dinv[i] * (hs[i] + sum_{s in in(i)} hs[s]) + bias )
template<int C, bool RELU>
__global__ void aggregate_kernel(const float* __restrict__ bias,
                                 float* __restrict__ outParam) {
    constexpr int V = C / 32;              // floats per lane (4 or 2)
    int gw = (blockIdx.x * blockDim.x + threadIdx.x) >> 5;
    if (gw >= NN) return;
    int lane = threadIdx.x & 31;
    int off  = lane * V;

    const float* hs;
    float*       out;
    if constexpr (RELU) { hs = g_hs1; out = g_h2; }       // layer 1
    else                { hs = g_hs2; out = outParam; }   // layer 2

    float acc[V];
    {
        const float* p = hs + (size_t)gw * C + off;
        if constexpr (V == 4) {
            float4 t = *(const float4*)p;
            acc[0] = t.x; acc[1] = t.y; acc[2] = t.z; acc[3] = t.w;
        } else {
            float2 t = *(const float2*)p;
            acc[0] = t.x; acc[1] = t.y;
        }
    }

    int s = g_rowptr[gw];
    int e = g_rowptr[gw + 1];
    for (int i = s; i < e; i++) {
        int src = g_col[i];
        const float* p = hs + (size_t)src * C + off;
        if constexpr (V == 4) {
            float4 t = *(const float4*)p;
            acc[0] += t.x; acc[1] += t.y; acc[2] += t.z; acc[3] += t.w;
        } else {
            float2 t = *(const float2*)p;
            acc[0] += t.x; acc[1] += t.y;
        }
    }

    float di = g_dinv[gw];
    float r[V];
    #pragma unroll
    for (int v = 0; v < V; v++) {
        float val = fmaf(acc[v], di, bias[off + v]);
        if (RELU) val = fmaxf(val, 0.f);
        r[v] = val;
    }
    float* q = out + (size_t)gw * C + off;
    if constexpr (V == 4) *(float4*)q = make_float4(r[0], r[1], r[2], r[3]);
    else                  *(float2*)q = make_float2(r[0], r[1]);
}

// ---------------- launch ------------------------------------------------------
extern "C" void kernel_launch(void* const* d_in, const int* in_sizes, int n_in,
                              void* d_out, int out_size) {
    const float* x  = (const float*)d_in[0];
    const void*  ei = d_in[1];                 // int64 (or int32) [2, E]
    const float* W1 = (const float*)d_in[2];
    const float* b1 = (const float*)d_in[3];
    const float* W2 = (const float*)d_in[4];
    const float* b2 = (const float*)d_in[5];
    float* out = (float*)d_out;

    // CSR build
    detect_kernel<<<1, 32>>>((const long long*)ei);
    zero_deg_kernel<<<(NN + 255) / 256, 256>>>();
    count_deg_kernel<<<(NE + 255) / 256, 256>>>(ei);
    dinv_kernel<<<(NN + 255) / 256, 256>>>();
    scan_kernel<<<1, 1024>>>();
    scatter_kernel<<<(NE + 255) / 256, 256>>>(ei);

    // layer 1: hs1 = dinv * (x @ W1);  h2 = relu(dinv * (A_sum hs1) + b1)
    constexpr int G1 = (NN + 63) / 64;     // 469
    gemm_dinv_kernel<64, 128, 16, C_IN, 1><<<G1, 256>>>(x, W1);
    aggregate_kernel<C_HID, true><<<(NN * 32 + 255) / 256, 256>>>(b1, nullptr);

    // layer 2: hs2 = dinv * (h2 @ W2);  out = dinv * (A_sum hs2) + b2
    constexpr int G2 = (NN + 127) / 128;   // 235
    gemm_dinv_kernel<128, 64, 16, C_HID, 2><<<G2, 256>>>(nullptr, W2);
    aggregate_kernel<C_OUT, false><<<(NN * 32 + 255) / 256, 256>>>(b2, out);
}